// round 7
// baseline (speedup 1.0000x reference)
#include <cuda_runtime.h>
#include <math.h>

// Problem constants
#define B   32
#define QL  16
#define KL  8192
#define D   512
#define INV_SQRT_D 0.044194173824159216f   // 1/sqrt(512)

// score kernel split (finer for wave balance / occupancy)
#define KSPLIT_S 64
#define KCHUNK_S (KL / KSPLIT_S)   // 128
// av kernel split
#define KSPLIT_V 32
#define KCHUNK_V (KL / KSPLIT_V)   // 256

// Scratch (device globals; allocations forbidden)
__device__ float g_w[B * KL];                  // 1 MB: p_k = exp(s_k) * t_k
__device__ float g_z[B * KSPLIT_S];            // per-chunk partial sums of p
__device__ float g_acc[B * KSPLIT_V * D];      // 2 MB: weighted-V partials

// ---------------------------------------------------------------------------
// Kernel A: p[b,k] = exp( (q0.key[b,k])/sqrt(D) * t[b,k] ) * t[b,k]
// No max subtraction: s ~ N(0,1)*t, exp() cannot overflow fp32.
// 2 rows per warp iteration; __launch_bounds__(256,6) caps regs at 42 so SIX
// blocks (48 warps) fit per SM (R6 analysis: DRAM% tracks resident warps,
// not per-warp MLP).
// grid (KSPLIT_S, B), block 256 (8 warps).
// ---------------------------------------------------------------------------
__global__ void __launch_bounds__(256, 6)
score_kernel(const float* __restrict__ q,
             const float* __restrict__ key,
             const float* __restrict__ trust)
{
    const int b  = blockIdx.y;
    const int k0 = blockIdx.x * KCHUNK_S;
    const int tid  = threadIdx.x;
    const int warp = tid >> 5;
    const int lane = tid & 31;

    __shared__ __align__(16) float qs[D];   // 2 KB
    __shared__ float red[8];

    const float* qb = q + (size_t)b * QL * D;      // query[b, 0, :]
    for (int i = tid; i < D; i += 256) qs[i] = qb[i];
    __syncthreads();

    const float4* qs4 = (const float4*)qs;
    const float*  tb  = trust + (size_t)b * KL + k0;
    float*        wb  = g_w   + (size_t)b * KL + k0;
    const float*  kbase = key + ((size_t)b * KL + k0) * D;

    float zloc = 0.0f;   // valid on lane 0
    for (int kk = warp * 2; kk < KCHUNK_S; kk += 16) {
        const float4* kv0 = (const float4*)(kbase + (size_t)(kk    ) * D);
        const float4* kv1 = (const float4*)(kbase + (size_t)(kk + 1) * D);
        float acc0 = 0.0f, acc1 = 0.0f;
        #pragma unroll
        for (int i = 0; i < 4; i++) {
            float4 qv = qs4[lane + i * 32];
            float4 a  = kv0[lane + i * 32];
            float4 c  = kv1[lane + i * 32];
            acc0 += a.x * qv.x + a.y * qv.y + a.z * qv.z + a.w * qv.w;
            acc1 += c.x * qv.x + c.y * qv.y + c.z * qv.z + c.w * qv.w;
        }
        #pragma unroll
        for (int o = 16; o > 0; o >>= 1) {
            acc0 += __shfl_xor_sync(0xffffffffu, acc0, o);
            acc1 += __shfl_xor_sync(0xffffffffu, acc1, o);
        }
        if (lane == 0) {
            float t0 = tb[kk], t1 = tb[kk + 1];
            float p0 = __expf(acc0 * INV_SQRT_D * t0) * t0;
            float p1 = __expf(acc1 * INV_SQRT_D * t1) * t1;
            wb[kk]     = p0;
            wb[kk + 1] = p1;
            zloc += p0 + p1;
        }
    }

    // block-level z partial (fixed order: warp 0..7)
    if (lane == 0) red[warp] = zloc;
    __syncthreads();
    if (warp == 0 && lane == 0) {
        float z = 0.0f;
        #pragma unroll
        for (int i = 0; i < 8; i++) z += red[i];
        g_z[b * KSPLIT_S + blockIdx.x] = z;
    }
}

// ---------------------------------------------------------------------------
// Kernel B: split-K weighted value sum (unnormalized weights).
// grid (KSPLIT_V, B), block 128; thread owns one float4 column, loops 256 rows.
// ---------------------------------------------------------------------------
__global__ void __launch_bounds__(128)
av_kernel(const float* __restrict__ value)
{
    const int b  = blockIdx.y;
    const int k0 = blockIdx.x * KCHUNK_V;

    __shared__ float ws[KCHUNK_V];
    for (int i = threadIdx.x; i < KCHUNK_V; i += 128)
        ws[i] = g_w[b * KL + k0 + i];
    __syncthreads();

    const float4* vb = (const float4*)(value + ((size_t)b * KL + k0) * D) + threadIdx.x;

    float4 acc = make_float4(0.0f, 0.0f, 0.0f, 0.0f);
    #pragma unroll 16
    for (int kk = 0; kk < KCHUNK_V; kk++) {
        float4 v = vb[(size_t)kk * (D / 4)];
        float  w = ws[kk];
        acc.x += w * v.x;
        acc.y += w * v.y;
        acc.z += w * v.z;
        acc.w += w * v.w;
    }

    float4* out4 = (float4*)(g_acc + ((size_t)(b * KSPLIT_V + blockIdx.x)) * D);
    out4[threadIdx.x] = acc;
}

// ---------------------------------------------------------------------------
// Kernel C: out[b,d] = (sum_i acc_i[d]) / (sum_j z_j)
// grid (128), block 128.
// ---------------------------------------------------------------------------
__global__ void __launch_bounds__(128)
reduce_kernel(float* __restrict__ out)
{
    const int idx = blockIdx.x * 128 + threadIdx.x;   // b*D + d
    const int b = idx >> 9;                           // /512
    __shared__ float invZ_s;

    if (threadIdx.x < 32) {
        // 64 z-partials per batch: fixed pairing keeps determinism
        float z = g_z[b * KSPLIT_S + threadIdx.x]
                + g_z[b * KSPLIT_S + 32 + threadIdx.x];
        #pragma unroll
        for (int o = 16; o > 0; o >>= 1)
            z += __shfl_xor_sync(0xffffffffu, z, o);
        if (threadIdx.x == 0) invZ_s = 1.0f / z;
    }
    __syncthreads();

    float acc = 0.0f;
    #pragma unroll
    for (int i = 0; i < KSPLIT_V; i++)
        acc += g_acc[(size_t)(b * KSPLIT_V + i) * D + (idx & (D - 1))];
    out[idx] = acc * invZ_s;
}

// ---------------------------------------------------------------------------
extern "C" void kernel_launch(void* const* d_in, const int* in_sizes, int n_in,
                              void* d_out, int out_size)
{
    const float* query = (const float*)d_in[0];   // (B, QL, D)
    const float* key   = (const float*)d_in[1];   // (B, KL, D)
    const float* value = (const float*)d_in[2];   // (B, KL, D)
    const float* trust = (const float*)d_in[3];   // (B, 1, KL)
    float* out = (float*)d_out;                   // (B, 1, D)

    (void)in_sizes; (void)n_in; (void)out_size;

    dim3 g1(KSPLIT_S, B);
    score_kernel<<<g1, 256>>>(query, key, trust);

    dim3 g2(KSPLIT_V, B);
    av_kernel<<<g2, 128>>>(value);

    reduce_kernel<<<(B * D) / 128, 128>>>(out);
}

// round 8
// speedup vs baseline: 1.0320x; 1.0320x over previous
#include <cuda_runtime.h>
#include <math.h>

// Problem constants
#define B   32
#define QL  16
#define KL  8192
#define D   512
#define INV_SQRT_D 0.044194173824159216f   // 1/sqrt(512)

// score: persistent grid, 64-row work units
#define SGRID  740                  // 148 SMs x 5 resident blocks -> zero waves
#define UROWS  64
#define UNITS  (B * KL / UROWS)     // 4096; u>>7 = b, (u&127)*64 = k0
#define ZPW    8                    // z partials per unit (one per warp)

// av kernel split
#define KSPLIT_V 32
#define KCHUNK_V (KL / KSPLIT_V)    // 256

// Scratch (device globals; allocations forbidden)
__device__ float g_w[B * KL];                  // 1 MB: p_k = exp(s_k) * t_k
__device__ float g_z[UNITS * ZPW];             // per-(unit,warp) partial sums
__device__ float g_acc[B * KSPLIT_V * D];      // 2 MB: weighted-V partials

// ---------------------------------------------------------------------------
// Kernel A (persistent): p[b,k] = exp((q0.key)/sqrt(D) * t) * t
// 740 blocks, all resident simultaneously -> no wave tail (R7 analysis: the
// 1.38-wave structure, not MLP or occupancy, capped DRAM at 78%).
// Each block owns a contiguous, balanced range of 64-row units.
// ---------------------------------------------------------------------------
__global__ void __launch_bounds__(256, 5)
score_kernel(const float* __restrict__ q,
             const float* __restrict__ key,
             const float* __restrict__ trust)
{
    const int tid  = threadIdx.x;
    const int warp = tid >> 5;
    const int lane = tid & 31;

    __shared__ __align__(16) float qs[D];   // 2 KB

    const int u0 = (int)(((long long)blockIdx.x       * UNITS) / SGRID);
    const int u1 = (int)(((long long)(blockIdx.x + 1) * UNITS) / SGRID);

    const float4* qs4 = (const float4*)qs;
    int bcur = -1;

    for (int u = u0; u < u1; u++) {
        const int b  = u >> 7;
        const int k0 = (u & 127) << 6;

        if (b != bcur) {
            __syncthreads();                       // qs readers done
            const float* qb = q + (size_t)b * QL * D;   // query[b,0,:]
            for (int i = tid; i < D; i += 256) qs[i] = qb[i];
            __syncthreads();
            bcur = b;
        }

        const float* kbase = key   + ((size_t)b * KL + k0) * D;
        const float* tb    = trust + (size_t)b * KL + k0;
        float*       wb    = g_w   + (size_t)b * KL + k0;

        float zloc = 0.0f;   // valid on lane 0
        #pragma unroll
        for (int kk = warp * 2; kk < UROWS; kk += 16) {
            const float4* kv0 = (const float4*)(kbase + (size_t)(kk    ) * D);
            const float4* kv1 = (const float4*)(kbase + (size_t)(kk + 1) * D);
            float acc0 = 0.0f, acc1 = 0.0f;
            #pragma unroll
            for (int i = 0; i < 4; i++) {
                float4 qv = qs4[lane + i * 32];
                float4 a  = kv0[lane + i * 32];
                float4 c  = kv1[lane + i * 32];
                acc0 += a.x * qv.x + a.y * qv.y + a.z * qv.z + a.w * qv.w;
                acc1 += c.x * qv.x + c.y * qv.y + c.z * qv.z + c.w * qv.w;
            }
            #pragma unroll
            for (int o = 16; o > 0; o >>= 1) {
                acc0 += __shfl_xor_sync(0xffffffffu, acc0, o);
                acc1 += __shfl_xor_sync(0xffffffffu, acc1, o);
            }
            if (lane == 0) {
                float t0 = tb[kk], t1 = tb[kk + 1];
                float p0 = __expf(acc0 * INV_SQRT_D * t0) * t0;
                float p1 = __expf(acc1 * INV_SQRT_D * t1) * t1;
                wb[kk]     = p0;
                wb[kk + 1] = p1;
                zloc += p0 + p1;
            }
        }
        if (lane == 0) g_z[u * ZPW + warp] = zloc;   // no block barrier needed
    }
}

// ---------------------------------------------------------------------------
// Kernel B: split-K weighted value sum (unnormalized weights).
// grid (KSPLIT_V, B), block 128 -> all 1024 blocks resident in one wave.
// ---------------------------------------------------------------------------
__global__ void __launch_bounds__(128)
av_kernel(const float* __restrict__ value)
{
    const int b  = blockIdx.y;
    const int k0 = blockIdx.x * KCHUNK_V;

    __shared__ float ws[KCHUNK_V];
    for (int i = threadIdx.x; i < KCHUNK_V; i += 128)
        ws[i] = g_w[b * KL + k0 + i];
    __syncthreads();

    const float4* vb = (const float4*)(value + ((size_t)b * KL + k0) * D) + threadIdx.x;

    float4 acc = make_float4(0.0f, 0.0f, 0.0f, 0.0f);
    #pragma unroll 16
    for (int kk = 0; kk < KCHUNK_V; kk++) {
        float4 v = vb[(size_t)kk * (D / 4)];
        float  w = ws[kk];
        acc.x += w * v.x;
        acc.y += w * v.y;
        acc.z += w * v.z;
        acc.w += w * v.w;
    }

    float4* out4 = (float4*)(g_acc + ((size_t)(b * KSPLIT_V + blockIdx.x)) * D);
    out4[threadIdx.x] = acc;
}

// ---------------------------------------------------------------------------
// Kernel C: out[b,d] = (sum_i acc_i[d]) / (sum_j z_j)
// grid (128), block 128. Z = fixed-order sum of the 1024 z partials per batch.
// ---------------------------------------------------------------------------
__global__ void __launch_bounds__(128)
reduce_kernel(float* __restrict__ out)
{
    const int idx = blockIdx.x * 128 + threadIdx.x;   // b*D + d
    const int b = idx >> 9;                           // /512
    __shared__ float invZ_s;

    if (threadIdx.x < 32) {
        // 1024 partials per batch: lane t sums entries t, t+32, ... (fixed order)
        const float* zb = g_z + (size_t)b * 128 * ZPW;  // 128 units * 8 warps
        float z = 0.0f;
        #pragma unroll
        for (int i = 0; i < 32; i++) z += zb[threadIdx.x + i * 32];
        #pragma unroll
        for (int o = 16; o > 0; o >>= 1)
            z += __shfl_xor_sync(0xffffffffu, z, o);
        if (threadIdx.x == 0) invZ_s = 1.0f / z;
    }
    __syncthreads();

    float acc = 0.0f;
    #pragma unroll
    for (int i = 0; i < KSPLIT_V; i++)
        acc += g_acc[(size_t)(b * KSPLIT_V + i) * D + (idx & (D - 1))];
    out[idx] = acc * invZ_s;
}

// ---------------------------------------------------------------------------
extern "C" void kernel_launch(void* const* d_in, const int* in_sizes, int n_in,
                              void* d_out, int out_size)
{
    const float* query = (const float*)d_in[0];   // (B, QL, D)
    const float* key   = (const float*)d_in[1];   // (B, KL, D)
    const float* value = (const float*)d_in[2];   // (B, KL, D)
    const float* trust = (const float*)d_in[3];   // (B, 1, KL)
    float* out = (float*)d_out;                   // (B, 1, D)

    (void)in_sizes; (void)n_in; (void)out_size;

    score_kernel<<<SGRID, 256>>>(query, key, trust);

    dim3 g2(KSPLIT_V, B);
    av_kernel<<<g2, 128>>>(value);

    reduce_kernel<<<(B * D) / 128, 128>>>(out);
}

// round 10
// speedup vs baseline: 1.0567x; 1.0239x over previous
#include <cuda_runtime.h>
#include <math.h>

// Problem constants
#define B   32
#define QL  16
#define KL  8192
#define D   512
#define INV_SQRT_D 0.044194173824159216f   // 1/sqrt(512)

// score kernel: av-style column streaming
#define KSPLIT_S 32
#define KCHUNK_S (KL / KSPLIT_S)   // 256 rows per block
#define TROWS    8                 // rows per smem tile
#define NTILES   (KCHUNK_S / TROWS)  // 32
#define ZPB      4                 // z partials per block (one per warp)

// av kernel split
#define KSPLIT_V 32
#define KCHUNK_V (KL / KSPLIT_V)   // 256

// Scratch (device globals; allocations forbidden)
__device__ float g_w[B * KL];                      // 1 MB: p_k = exp(s_k)*t_k
__device__ float g_z[B * KSPLIT_S * ZPB];          // per-(block,warp) z partials
__device__ float g_acc[B * KSPLIT_V * D];          // 2 MB: weighted-V partials

// ---------------------------------------------------------------------------
// Kernel A: p[b,k] = exp((q0.key[b,k])/sqrt(D)*t) * t  — av-style streaming.
// 128 threads; thread t owns float4 column t and streams rows sequentially
// (the ONLY pattern that has demonstrated >=7 TB/s on this chip: per-thread
// sequential column loads, no cross-lane dependence in the load path).
// Per-row dot partials go through double-buffered smem tiles; the cross-
// thread reduction (LDS.128 + shuffles) overlaps the next tile's prefetch.
// grid (KSPLIT_S, B), block 128 — identical launch geometry to av.
// ---------------------------------------------------------------------------
__global__ void __launch_bounds__(128, 8)
score_kernel(const float* __restrict__ q,
             const float* __restrict__ key,
             const float* __restrict__ trust)
{
    const int b   = blockIdx.y;
    const int k0  = blockIdx.x * KCHUNK_S;
    const int tid = threadIdx.x;
    const int warp = tid >> 5;
    const int lane = tid & 31;

    __shared__ __align__(16) float ps[2][TROWS][128];   // 8 KB partial tiles
    __shared__ float ts[KCHUNK_S];                      // 1 KB trust chunk

    // q column held in registers for the whole kernel
    const float4 q4 = ((const float4*)(q + (size_t)b * QL * D))[tid];

    for (int i = tid; i < KCHUNK_S; i += 128)
        ts[i] = trust[(size_t)b * KL + k0 + i];

    // thread's column stream: row stride = D/4 = 128 float4
    const float4* kb = (const float4*)(key + ((size_t)b * KL + k0) * D) + tid;
    float* wb = g_w + (size_t)b * KL + k0;

    float zloc = 0.0f;          // valid on lane 0 of each warp
    float4 r[TROWS];

    // prologue: tile 0 -> buf 0
    #pragma unroll
    for (int j = 0; j < TROWS; j++) r[j] = kb[(size_t)j * (D / 4)];
    #pragma unroll
    for (int j = 0; j < TROWS; j++)
        ps[0][j][tid] = (r[j].x * q4.x + r[j].y * q4.y)
                      + (r[j].z * q4.z + r[j].w * q4.w);
    __syncthreads();

    for (int t = 0; t < NTILES; t++) {
        // prefetch next tile (8 independent, sequential LDG.128)
        if (t + 1 < NTILES) {
            const float4* kn = kb + (size_t)(t + 1) * TROWS * (D / 4);
            #pragma unroll
            for (int j = 0; j < TROWS; j++) r[j] = kn[(size_t)j * (D / 4)];
        }

        // reduce tile t: warp w handles rows 2w, 2w+1
        const int buf = t & 1;
        #pragma unroll
        for (int rr = 0; rr < 2; rr++) {
            const int row = warp * 2 + rr;
            float4 v = ((const float4*)ps[buf][row])[lane];
            float s = (v.x + v.y) + (v.z + v.w);
            #pragma unroll
            for (int o = 16; o > 0; o >>= 1)
                s += __shfl_xor_sync(0xffffffffu, s, o);
            if (lane == 0) {
                const int gk = t * TROWS + row;
                const float tt = ts[gk];
                const float p = __expf(s * INV_SQRT_D * tt) * tt;
                wb[gk] = p;
                zloc += p;
            }
        }

        // stage next tile's partials into the other buffer
        if (t + 1 < NTILES) {
            const int nbuf = (t + 1) & 1;
            #pragma unroll
            for (int j = 0; j < TROWS; j++)
                ps[nbuf][j][tid] = (r[j].x * q4.x + r[j].y * q4.y)
                                 + (r[j].z * q4.z + r[j].w * q4.w);
        }
        __syncthreads();
    }

    if (lane == 0)
        g_z[(size_t)(b * KSPLIT_S + blockIdx.x) * ZPB + warp] = zloc;
}

// ---------------------------------------------------------------------------
// Kernel B: split-K weighted value sum (unnormalized weights). Unchanged —
// this pattern is the >=7 TB/s reference.
// grid (KSPLIT_V, B), block 128.
// ---------------------------------------------------------------------------
__global__ void __launch_bounds__(128)
av_kernel(const float* __restrict__ value)
{
    const int b  = blockIdx.y;
    const int k0 = blockIdx.x * KCHUNK_V;

    __shared__ float ws[KCHUNK_V];
    for (int i = threadIdx.x; i < KCHUNK_V; i += 128)
        ws[i] = g_w[b * KL + k0 + i];
    __syncthreads();

    const float4* vb = (const float4*)(value + ((size_t)b * KL + k0) * D) + threadIdx.x;

    float4 acc = make_float4(0.0f, 0.0f, 0.0f, 0.0f);
    #pragma unroll 16
    for (int kk = 0; kk < KCHUNK_V; kk++) {
        float4 v = vb[(size_t)kk * (D / 4)];
        float  w = ws[kk];
        acc.x += w * v.x;
        acc.y += w * v.y;
        acc.z += w * v.z;
        acc.w += w * v.w;
    }

    float4* out4 = (float4*)(g_acc + ((size_t)(b * KSPLIT_V + blockIdx.x)) * D);
    out4[threadIdx.x] = acc;
}

// ---------------------------------------------------------------------------
// Kernel C: out[b,d] = (sum_i acc_i[d]) / (sum_j z_j)
// grid (128), block 128. 128 z partials per batch, fixed-order sum.
// ---------------------------------------------------------------------------
__global__ void __launch_bounds__(128)
reduce_kernel(float* __restrict__ out)
{
    const int idx = blockIdx.x * 128 + threadIdx.x;   // b*D + d
    const int b = idx >> 9;                           // /512
    __shared__ float invZ_s;

    if (threadIdx.x < 32) {
        const float* zb = g_z + (size_t)b * KSPLIT_S * ZPB;   // 128 entries
        float z = 0.0f;
        #pragma unroll
        for (int i = 0; i < 4; i++) z += zb[threadIdx.x + i * 32];
        #pragma unroll
        for (int o = 16; o > 0; o >>= 1)
            z += __shfl_xor_sync(0xffffffffu, z, o);
        if (threadIdx.x == 0) invZ_s = 1.0f / z;
    }
    __syncthreads();

    float acc = 0.0f;
    #pragma unroll
    for (int i = 0; i < KSPLIT_V; i++)
        acc += g_acc[(size_t)(b * KSPLIT_V + i) * D + (idx & (D - 1))];
    out[idx] = acc * invZ_s;
}

// ---------------------------------------------------------------------------
extern "C" void kernel_launch(void* const* d_in, const int* in_sizes, int n_in,
                              void* d_out, int out_size)
{
    const float* query = (const float*)d_in[0];   // (B, QL, D)
    const float* key   = (const float*)d_in[1];   // (B, KL, D)
    const float* value = (const float*)d_in[2];   // (B, KL, D)
    const float* trust = (const float*)d_in[3];   // (B, 1, KL)
    float* out = (float*)d_out;                   // (B, 1, D)

    (void)in_sizes; (void)n_in; (void)out_size;

    dim3 g1(KSPLIT_S, B);
    score_kernel<<<g1, 128>>>(query, key, trust);

    dim3 g2(KSPLIT_V, B);
    av_kernel<<<g2, 128>>>(value);

    reduce_kernel<<<(B * D) / 128, 128>>>(out);
}